// round 6
// baseline (speedup 1.0000x reference)
#include <cuda_runtime.h>

#define DECAY 0.95122942450071400909f   // exp(-1/20)

// ---------------- persistent state (device globals; no allocation) ----------
__device__ float g_vm0[16*32*64*64];
__device__ float g_s0 [16*32*64*64];
__device__ float g_vm1[16*64*64*64];
__device__ float g_s1 [16*64*64*64];
__device__ float g_vm2[16*512];
__device__ float g_s2 [16*512];
__device__ float g_vm3[16*11];
__device__ float g_s3 [16*11];
__device__ float g_acc[16*11];
__device__ unsigned short g_flags[65536];   // bit b = pooled spike of batch b at feature k

// ---------------- zero all state --------------------------------------------
__global__ void k_zero() {
    int i = blockIdx.x * blockDim.x + threadIdx.x;
    int stride = gridDim.x * blockDim.x;
    for (int k = i; k < 16*32*64*64; k += stride) { g_vm0[k] = 0.f; g_s0[k] = 0.f; }
    for (int k = i; k < 16*64*64*64; k += stride) { g_vm1[k] = 0.f; g_s1[k] = 0.f; }
    for (int k = i; k < 16*512;      k += stride) { g_vm2[k] = 0.f; g_s2[k] = 0.f; }
    for (int k = i; k < 176;         k += stride) { g_vm3[k] = 0.f; g_s3[k] = 0.f; g_acc[k] = 0.f; }
}

// ---------------- conv0 (2->32, 3x3, pad1) + LIF0 ---------------------------
// grid (4,4,16) blocks of (16,16); one 16x16 spatial tile per block, all 32 co.
__global__ void __launch_bounds__(256) k_conv0(const float* __restrict__ input,
                                               const float* __restrict__ W0, int t) {
    __shared__ float sin_[2*18*18];
    __shared__ float sw[576];                 // [co][ci][ky][kx] native layout
    int b  = blockIdx.z, bx = blockIdx.x, by = blockIdx.y;
    int tx = threadIdx.x, ty = threadIdx.y;
    int tid = ty * 16 + tx;

    for (int i = tid; i < 576; i += 256) sw[i] = W0[i];

    const float* inb = input + (size_t)((b*16 + t) * 2) * 4096;
    for (int i = tid; i < 2*18*18; i += 256) {
        int ci = i / 324, r = i - ci*324;
        int yy = r / 18,  xx = r - yy*18;
        int gy = by*16 + yy - 1, gx = bx*16 + xx - 1;
        float v = 0.f;
        if ((unsigned)gy < 64u && (unsigned)gx < 64u) {
            v = inb[ci*4096 + gy*64 + gx];
            v = fminf(fmaxf(v, 0.f), 1.f);    // limit=1 -> clip to [0,1]
        }
        sin_[i] = v;
    }
    __syncthreads();

    int gy = by*16 + ty, gx = bx*16 + tx;
    for (int co = 0; co < 32; co++) {
        float acc = 0.f;
        #pragma unroll
        for (int ci = 0; ci < 2; ci++)
            #pragma unroll
            for (int ky = 0; ky < 3; ky++)
                #pragma unroll
                for (int kx = 0; kx < 3; kx++)
                    acc += sin_[ci*324 + (ty+ky)*18 + (tx+kx)] * sw[(co*2+ci)*9 + ky*3 + kx];
        int idx = ((b*32 + co) << 12) + (gy << 6) + gx;
        float v  = g_vm0[idx];
        float sp = g_s0[idx];
        v = v * DECAY * (1.f - sp) + acc;
        g_vm0[idx] = v;
        g_s0[idx]  = (v > 0.5f) ? 1.f : 0.f;
    }
}

// ---------------- conv1 (32->64, 3x3, pad1) + LIF1 ---------------------------
// grid (4,8,16) blocks of (16,8); 16x8 spatial tile, all 64 co via f32x2 packed FMA.
// dyn smem: s_tile [32][10][18] (5760 f) + weights [ci*9+kk][64co] (18432 f) = 96768 B
__global__ void __launch_bounds__(128) k_conv1(const float* __restrict__ W1) {
    extern __shared__ float sm[];
    float* stile = sm;                 // 5760 floats
    float* wsh   = sm + 5760;          // 18432 floats, co-contiguous

    int b  = blockIdx.z, bx = blockIdx.x, by = blockIdx.y;
    int tx = threadIdx.x, ty = threadIdx.y;
    int tid = ty * 16 + tx;

    for (int i = tid; i < 18432; i += 128) {
        int q = i >> 6, co = i & 63;          // q = ci*9+kk
        int ci = q / 9, kk = q - ci*9;
        wsh[i] = W1[(co*32 + ci)*9 + kk];
    }
    for (int i = tid; i < 5760; i += 128) {
        int ci = i / 180, r = i - ci*180;
        int yy = r / 18,  xx = r - yy*18;
        int gy = by*8 + yy - 1, gx = bx*16 + xx - 1;
        float v = 0.f;
        if ((unsigned)gy < 64u && (unsigned)gx < 64u)
            v = g_s0[((b*32 + ci) << 12) + (gy << 6) + gx];
        stile[i] = v;
    }
    __syncthreads();

    unsigned long long acc[32];
    #pragma unroll
    for (int i = 0; i < 32; i++) acc[i] = 0ull;

    for (int ci = 0; ci < 32; ci++) {
        #pragma unroll
        for (int kk = 0; kk < 9; kk++) {
            int ky = kk / 3, kx = kk - ky*3;
            float sv = stile[ci*180 + (ty+ky)*18 + (tx+kx)];
            unsigned act = __ballot_sync(0xffffffffu, sv != 0.f);
            if (act == 0u) continue;          // whole warp sees silent inputs
            unsigned long long sv2;
            asm("mov.b64 %0, {%1, %1};" : "=l"(sv2) : "f"(sv));
            const unsigned long long* wrow =
                reinterpret_cast<const unsigned long long*>(wsh + (ci*9 + kk)*64);
            #pragma unroll
            for (int c2 = 0; c2 < 32; c2++)
                asm("fma.rn.f32x2 %0, %1, %2, %0;" : "+l"(acc[c2]) : "l"(sv2), "l"(wrow[c2]));
        }
    }

    int gy = by*8 + ty, gx = bx*16 + tx;
    #pragma unroll
    for (int c2 = 0; c2 < 32; c2++) {
        float lo, hi;
        asm("mov.b64 {%0, %1}, %2;" : "=f"(lo), "=f"(hi) : "l"(acc[c2]));
        int co = 2*c2;
        {
            int idx = ((b*64 + co) << 12) + (gy << 6) + gx;
            float v = g_vm1[idx], sp = g_s1[idx];
            v = v * DECAY * (1.f - sp) + lo;
            g_vm1[idx] = v;
            g_s1[idx]  = (v > 0.5f) ? 1.f : 0.f;
        }
        {
            int idx = ((b*64 + co + 1) << 12) + (gy << 6) + gx;
            float v = g_vm1[idx], sp = g_s1[idx];
            v = v * DECAY * (1.f - sp) + hi;
            g_vm1[idx] = v;
            g_s1[idx]  = (v > 0.5f) ? 1.f : 0.f;
        }
    }
}

// ---------------- maxpool 2x2 + pack 16 batch bits per feature --------------
__global__ void k_pool() {
    int k = blockIdx.x * 256 + threadIdx.x;          // 65536 features
    int c = k >> 10, r = k & 1023, y = r >> 5, x = r & 31;
    unsigned bits = 0;
    #pragma unroll
    for (int b = 0; b < 16; b++) {
        const float* p = g_s1 + ((b*64 + c) << 12) + ((2*y) << 6) + 2*x;
        float m = fmaxf(fmaxf(p[0], p[1]), fmaxf(p[64], p[65]));
        bits |= (m > 0.5f) ? (1u << b) : 0u;
    }
    g_flags[k] = (unsigned short)bits;
}

// ---------------- dense0 (65536 -> 512) + LIF2 -------------------------------
// one block per output row j; thread-strided K, 16 batch accumulators.
__global__ void __launch_bounds__(256) k_dense0(const float* __restrict__ D0) {
    __shared__ float red[256*16];
    int j   = blockIdx.x;
    int tid = threadIdx.x;
    const float* row = D0 + (size_t)j * 65536;

    float acc[16];
    #pragma unroll
    for (int b = 0; b < 16; b++) acc[b] = 0.f;

    for (int k = tid; k < 65536; k += 256) {
        float w = row[k];
        unsigned f = g_flags[k];
        #pragma unroll
        for (int b = 0; b < 16; b++)
            if (f & (1u << b)) acc[b] += w;
    }

    #pragma unroll
    for (int b = 0; b < 16; b++) red[tid*16 + b] = acc[b];
    __syncthreads();
    for (int off = 128; off > 0; off >>= 1) {
        if (tid < off)
            #pragma unroll
            for (int b = 0; b < 16; b++)
                red[tid*16 + b] += red[(tid + off)*16 + b];
        __syncthreads();
    }
    if (tid < 16) {
        int b = tid;
        float I = red[b];
        int idx = b*512 + j;
        float v = g_vm2[idx], sp = g_s2[idx];
        v = v * DECAY * (1.f - sp) + I;
        g_vm2[idx] = v;
        g_s2[idx]  = (v > 0.5f) ? 1.f : 0.f;
    }
}

// ---------------- dense1 (512 -> 11) + LIF3 + acc ----------------------------
// single block, 704 threads: 176 outputs x 4-way K split.
__global__ void k_dense1(const float* __restrict__ D1) {
    __shared__ float red[176*4];
    int tid = threadIdx.x;
    int o = tid >> 2, q = tid & 3;
    float s = 0.f;
    int b = o / 11, i = o - b*11;
    const float* d1r = D1 + i*512;
    const float* s2r = g_s2 + b*512;
    #pragma unroll 8
    for (int k = q*128; k < q*128 + 128; k++)
        s += s2r[k] * d1r[k];
    red[o*4 + q] = s;
    __syncthreads();
    if (q == 0) {
        float I = red[o*4] + red[o*4+1] + red[o*4+2] + red[o*4+3];
        float v = g_vm3[o], sp = g_s3[o];
        v = v * DECAY * (1.f - sp) + I;
        g_vm3[o] = v;
        float sn = (v > 0.5f) ? 1.f : 0.f;
        g_s3[o] = sn;
        g_acc[o] += sn;
    }
}

// ---------------- finalize ----------------------------------------------------
__global__ void k_final(float* __restrict__ out) {
    int i = threadIdx.x;
    if (i < 176) out[i] = g_acc[i] * 0.0625f;   // / num_steps (=16)
}

// ---------------- launch -------------------------------------------------------
extern "C" void kernel_launch(void* const* d_in, const int* in_sizes, int n_in,
                              void* d_out, int out_size) {
    (void)in_sizes; (void)n_in; (void)out_size;
    const float* input = (const float*)d_in[0];
    const float* W0    = (const float*)d_in[1];
    const float* W1    = (const float*)d_in[2];
    const float* D0    = (const float*)d_in[3];
    const float* D1    = (const float*)d_in[4];

    // opt-in >48KB dynamic smem for conv1 — only when not capturing (the
    // correctness call runs first and persists the attribute).
    cudaStreamCaptureStatus cs = cudaStreamCaptureStatusNone;
    cudaStreamIsCapturing(0, &cs);
    if (cs == cudaStreamCaptureStatusNone)
        cudaFuncSetAttribute(k_conv1, cudaFuncAttributeMaxDynamicSharedMemorySize, 96768);

    k_zero<<<1024, 256>>>();

    for (int t = 0; t < 16; t++) {
        k_conv0<<<dim3(4,4,16), dim3(16,16)>>>(input, W0, t);
        k_conv1<<<dim3(4,8,16), dim3(16,8), 96768>>>(W1);
        k_pool<<<256, 256>>>();
        k_dense0<<<512, 256>>>(D0);
        k_dense1<<<1, 704>>>(D1);
    }
    k_final<<<1, 192>>>((float*)d_out);
}